// round 3
// baseline (speedup 1.0000x reference)
#include <cuda_runtime.h>
#include <cuda_bf16.h>
#include <cstdint>
#include <math.h>

#define NPTS     524288
#define NGRIDS   64
#define GVOX     262144      /* 64^3 */
#define PTS_CTA  128
#define THREADS  256

#define KS0 200              /* bf16 element stride, layer0 (k=192 used) */
#define KS1 72               /* bf16 element stride, layer1 (k=64 used)  */

// ---------------- smem layout (bytes) ----------------
#define SM_A0H 0
#define SM_A0L (SM_A0H + PTS_CTA * KS0 * 2)   /* 51200  */
#define SM_B0H (SM_A0L + PTS_CTA * KS0 * 2)   /* 102400 */
#define SM_B0L (SM_B0H + 64 * KS0 * 2)        /* 128000 */
#define SM_B1H (SM_B0L + 64 * KS0 * 2)        /* 153600 */
#define SM_B1L (SM_B1H + 64 * KS1 * 2)        /* 162816 */
#define SM_AUX (SM_B1L + 64 * KS1 * 2)        /* 172032 */
// aux floats: b0[64] @0, b1[64] @64, w2[64] @128, sc[192] @192, tr[192] @384
#define AUX_FLOATS 576
#define SMEM_TOTAL (SM_AUX + AUX_FLOATS * 4)  /* 174336 */

__device__ float2 g_packed[NGRIDS * GVOX];    // channel-interleaved volumes

// ---------------- helpers ----------------
__device__ __forceinline__ void mma16816(float* c, const uint32_t* a,
                                         uint32_t b0, uint32_t b1) {
    asm volatile(
        "mma.sync.aligned.m16n8k16.row.col.f32.bf16.bf16.f32 "
        "{%0,%1,%2,%3}, {%4,%5,%6,%7}, {%8,%9}, {%0,%1,%2,%3};"
        : "+f"(c[0]), "+f"(c[1]), "+f"(c[2]), "+f"(c[3])
        : "r"(a[0]), "r"(a[1]), "r"(a[2]), "r"(a[3]), "r"(b0), "r"(b1));
}
// split two floats into packed bf16 hi pair + lo (residual) pair
__device__ __forceinline__ void split2(float v0, float v1, uint32_t& hi,
                                       uint32_t& lo) {
    __nv_bfloat16 h0 = __float2bfloat16(v0), h1 = __float2bfloat16(v1);
    __nv_bfloat16 l0 = __float2bfloat16(v0 - __bfloat162float(h0));
    __nv_bfloat16 l1 = __float2bfloat16(v1 - __bfloat162float(h1));
    hi = ((uint32_t)__bfloat16_as_ushort(h1) << 16) | __bfloat16_as_ushort(h0);
    lo = ((uint32_t)__bfloat16_as_ushort(l1) << 16) | __bfloat16_as_ushort(l0);
}
__device__ __forceinline__ float snake(float h) {
    float s = __sinf(h);
    return fmaf(0.5f, h, s * s);
}

// ---------------- repack: [g][c][v] f32 -> [g][v] float2 ----------------
__global__ void repack4(const float* __restrict__ fg) {
    int idx = blockIdx.x * blockDim.x + threadIdx.x;  // 0 .. 4194303
    int g = idx >> 16;
    int v4 = (idx & 65535) << 2;
    const float4 a = *(const float4*)(fg + (size_t)(2 * g) * GVOX + v4);
    const float4 b = *(const float4*)(fg + (size_t)(2 * g + 1) * GVOX + v4);
    float2* o = g_packed + ((size_t)g << 18) + v4;
    *(float4*)(o + 0) = make_float4(a.x, b.x, a.y, b.y);
    *(float4*)(o + 2) = make_float4(a.z, b.z, a.w, b.w);
}

// ---------------- main fused kernel ----------------
__global__ void __launch_bounds__(THREADS, 1)
amrsrn_hmma(const float* __restrict__ x,
            const float* __restrict__ gscale,
            const float* __restrict__ gtrans,
            const float* __restrict__ W0,
            const float* __restrict__ b0,
            const float* __restrict__ W1,
            const float* __restrict__ b1,
            const float* __restrict__ W2,
            const float* __restrict__ b2,
            float* __restrict__ out) {
    extern __shared__ char smem[];
    float* auxf = (float*)(smem + SM_AUX);
    const int tid = threadIdx.x;

    // ---- stage weights as bf16 hi/lo, layout [n][k] (B col-major k x n) ----
    for (int i = tid; i < 64 * 96; i += THREADS) {
        int n = i & 63, k = (i >> 6) * 2;
        float v0 = (k < 164) ? W0[k * 64 + n] : 0.f;
        float v1 = (k + 1 < 164) ? W0[(k + 1) * 64 + n] : 0.f;
        uint32_t hi, lo;
        split2(v0, v1, hi, lo);
        *(uint32_t*)(smem + SM_B0H + (n * KS0 + k) * 2) = hi;
        *(uint32_t*)(smem + SM_B0L + (n * KS0 + k) * 2) = lo;
    }
    for (int i = tid; i < 64 * 32; i += THREADS) {
        int n = i & 63, j = (i >> 6) * 2;
        uint32_t hi, lo;
        split2(W1[j * 64 + n], W1[(j + 1) * 64 + n], hi, lo);
        *(uint32_t*)(smem + SM_B1H + (n * KS1 + j) * 2) = hi;
        *(uint32_t*)(smem + SM_B1L + (n * KS1 + j) * 2) = lo;
    }
    // zero A0 pad cols [164,192)
    for (int i = tid; i < PTS_CTA * 14; i += THREADS) {
        int r = i / 14, k = 164 + (i % 14) * 2;
        *(uint32_t*)(smem + SM_A0H + (r * KS0 + k) * 2) = 0u;
        *(uint32_t*)(smem + SM_A0L + (r * KS0 + k) * 2) = 0u;
    }
    for (int i = tid; i < 64; i += THREADS) {
        auxf[i] = b0[i];
        auxf[64 + i] = b1[i];
        auxf[128 + i] = W2[i];
    }
    for (int i = tid; i < 192; i += THREADS) {
        auxf[192 + i] = gscale[i];
        auxf[384 + i] = gtrans[i];
    }
    __syncthreads();

    // ---- feature phase: 2 threads per point ----
    const int p = tid & 127;
    const int half = tid >> 7;
    const int gpt = blockIdx.x * PTS_CTA + p;
    const float px = __ldg(&x[3 * gpt + 0]);
    const float py = __ldg(&x[3 * gpt + 1]);
    const float pz = __ldg(&x[3 * gpt + 2]);
    const float xyz[3] = {px, py, pz};

    // PE: half0 -> sin cols 0..17, half1 -> cos cols 18..35
    {
        float v[18];
#pragma unroll
        for (int l = 0; l < 6; l++) {
            float freq = 3.14159265358979323846f * (float)(1 << l);
#pragma unroll
            for (int d = 0; d < 3; d++) {
                float s, c;
                sincosf(xyz[d] * freq, &s, &c);
                v[l * 3 + d] = half ? c : s;
            }
        }
        int cb = half ? 18 : 0;
#pragma unroll
        for (int i = 0; i < 9; i++) {
            uint32_t hi, lo;
            split2(v[2 * i], v[2 * i + 1], hi, lo);
            *(uint32_t*)(smem + SM_A0H + (p * KS0 + cb + 2 * i) * 2) = hi;
            *(uint32_t*)(smem + SM_A0L + (p * KS0 + cb + 2 * i) * 2) = lo;
        }
    }

    // grid gather: half h handles grids [32h, 32h+32)
#pragma unroll 1
    for (int gi = 0; gi < 32; gi++) {
        int g = half * 32 + gi;
        float sx = auxf[192 + 3 * g + 0], sy = auxf[192 + 3 * g + 1],
              sz = auxf[192 + 3 * g + 2];
        float tx = auxf[384 + 3 * g + 0], ty = auxf[384 + 3 * g + 1],
              tz = auxf[384 + 3 * g + 2];
        float ix = fmaf(fmaf(px, sx, tx), 31.5f, 31.5f);
        float iy = fmaf(fmaf(py, sy, ty), 31.5f, 31.5f);
        float iz = fmaf(fmaf(pz, sz, tz), 31.5f, 31.5f);
        float f0 = 0.f, f1 = 0.f;
        if (ix > -1.f && ix < 64.f && iy > -1.f && iy < 64.f && iz > -1.f &&
            iz < 64.f) {
            float fx = floorf(ix), fy = floorf(iy), fz = floorf(iz);
            int X0 = (int)fx, Y0 = (int)fy, Z0 = (int)fz;
            float wx1 = ix - fx, wy1 = iy - fy, wz1 = iz - fz;
            float wx0 = 1.f - wx1, wy0 = 1.f - wy1, wz0 = 1.f - wz1;
            if (X0 < 0)   wx0 = 0.f;
            if (X0 >= 63) wx1 = 0.f;
            if (Y0 < 0)   wy0 = 0.f;
            if (Y0 >= 63) wy1 = 0.f;
            if (Z0 < 0)   wz0 = 0.f;
            if (Z0 >= 63) wz1 = 0.f;
            int x0c = max(X0, 0), x1c = min(X0 + 1, 63);
            int y0c = max(Y0, 0), y1c = min(Y0 + 1, 63);
            int z0c = max(Z0, 0), z1c = min(Z0 + 1, 63);
            const float2* vol = g_packed + ((size_t)g << 18);
            int b00 = (z0c << 12) + (y0c << 6);
            int b01 = (z0c << 12) + (y1c << 6);
            int b10 = (z1c << 12) + (y0c << 6);
            int b11 = (z1c << 12) + (y1c << 6);
            float2 v000 = __ldg(&vol[b00 + x0c]);
            float2 v001 = __ldg(&vol[b00 + x1c]);
            float2 v010 = __ldg(&vol[b01 + x0c]);
            float2 v011 = __ldg(&vol[b01 + x1c]);
            float2 v100 = __ldg(&vol[b10 + x0c]);
            float2 v101 = __ldg(&vol[b10 + x1c]);
            float2 v110 = __ldg(&vol[b11 + x0c]);
            float2 v111 = __ldg(&vol[b11 + x1c]);
            float w00 = wz0 * wy0, w01 = wz0 * wy1;
            float w10 = wz1 * wy0, w11 = wz1 * wy1;
            float c000 = w00 * wx0, c001 = w00 * wx1;
            float c010 = w01 * wx0, c011 = w01 * wx1;
            float c100 = w10 * wx0, c101 = w10 * wx1;
            float c110 = w11 * wx0, c111 = w11 * wx1;
            f0 = c000 * v000.x;
            f1 = c000 * v000.y;
            f0 = fmaf(c001, v001.x, f0); f1 = fmaf(c001, v001.y, f1);
            f0 = fmaf(c010, v010.x, f0); f1 = fmaf(c010, v010.y, f1);
            f0 = fmaf(c011, v011.x, f0); f1 = fmaf(c011, v011.y, f1);
            f0 = fmaf(c100, v100.x, f0); f1 = fmaf(c100, v100.y, f1);
            f0 = fmaf(c101, v101.x, f0); f1 = fmaf(c101, v101.y, f1);
            f0 = fmaf(c110, v110.x, f0); f1 = fmaf(c110, v110.y, f1);
            f0 = fmaf(c111, v111.x, f0); f1 = fmaf(c111, v111.y, f1);
        }
        uint32_t hi, lo;
        split2(f0, f1, hi, lo);
        int col = 36 + 2 * g;
        *(uint32_t*)(smem + SM_A0H + (p * KS0 + col) * 2) = hi;
        *(uint32_t*)(smem + SM_A0L + (p * KS0 + col) * 2) = lo;
    }

    __syncthreads();

    // ---- MMA phase: warp w owns points [16w, 16w+16), all 64 outputs ----
    const int lane = tid & 31;
    const int gid = lane >> 2;       // 0..7
    const int tid4 = lane & 3;       // 0..3
    const int p0 = (tid >> 5) * 16;
    const char* A0H = smem + SM_A0H;
    const char* A0L = smem + SM_A0L;
    const char* B0H = smem + SM_B0H;
    const char* B0L = smem + SM_B0L;
    const char* B1H = smem + SM_B1H;
    const char* B1L = smem + SM_B1L;

    float acc0[8][4];
#pragma unroll
    for (int nt = 0; nt < 8; nt++)
#pragma unroll
        for (int j = 0; j < 4; j++) acc0[nt][j] = 0.f;

    const int rA = (p0 + gid) * KS0;
    const int rA8 = (p0 + gid + 8) * KS0;
#pragma unroll 1
    for (int kt = 0; kt < 12; kt++) {
        const int k0 = kt * 16 + tid4 * 2;
        uint32_t aH[4], aL[4];
        aH[0] = *(const uint32_t*)(A0H + (rA + k0) * 2);
        aH[1] = *(const uint32_t*)(A0H + (rA8 + k0) * 2);
        aH[2] = *(const uint32_t*)(A0H + (rA + k0 + 8) * 2);
        aH[3] = *(const uint32_t*)(A0H + (rA8 + k0 + 8) * 2);
        aL[0] = *(const uint32_t*)(A0L + (rA + k0) * 2);
        aL[1] = *(const uint32_t*)(A0L + (rA8 + k0) * 2);
        aL[2] = *(const uint32_t*)(A0L + (rA + k0 + 8) * 2);
        aL[3] = *(const uint32_t*)(A0L + (rA8 + k0 + 8) * 2);
#pragma unroll
        for (int nt = 0; nt < 8; nt++) {
            const int rB = (nt * 8 + gid) * KS0;
            uint32_t bh0 = *(const uint32_t*)(B0H + (rB + k0) * 2);
            uint32_t bh1 = *(const uint32_t*)(B0H + (rB + k0 + 8) * 2);
            uint32_t bl0 = *(const uint32_t*)(B0L + (rB + k0) * 2);
            uint32_t bl1 = *(const uint32_t*)(B0L + (rB + k0 + 8) * 2);
            mma16816(acc0[nt], aH, bh0, bh1);
            mma16816(acc0[nt], aL, bh0, bh1);
            mma16816(acc0[nt], aH, bl0, bl1);
        }
    }

    // ---- epilogue 0: bias + snake -> layer1 A fragments (no smem) ----
    uint32_t a1H[4][4], a1L[4][4];
#pragma unroll
    for (int nt = 0; nt < 8; nt++) {
        int cb = nt * 8 + tid4 * 2;
        float ba = auxf[cb], bb = auxf[cb + 1];
        float v0 = snake(acc0[nt][0] + ba);
        float v1 = snake(acc0[nt][1] + bb);
        float v2 = snake(acc0[nt][2] + ba);
        float v3 = snake(acc0[nt][3] + bb);
        int kt1 = nt >> 1, h = (nt & 1) * 2;
        split2(v0, v1, a1H[kt1][h + 0], a1L[kt1][h + 0]);
        split2(v2, v3, a1H[kt1][h + 1], a1L[kt1][h + 1]);
    }

    // ---- layer 1 MMA ----
    float acc1[8][4];
#pragma unroll
    for (int nt = 0; nt < 8; nt++)
#pragma unroll
        for (int j = 0; j < 4; j++) acc1[nt][j] = 0.f;
#pragma unroll
    for (int kt = 0; kt < 4; kt++) {
        const int k0 = kt * 16 + tid4 * 2;
#pragma unroll
        for (int nt = 0; nt < 8; nt++) {
            const int rB = (nt * 8 + gid) * KS1;
            uint32_t bh0 = *(const uint32_t*)(B1H + (rB + k0) * 2);
            uint32_t bh1 = *(const uint32_t*)(B1H + (rB + k0 + 8) * 2);
            uint32_t bl0 = *(const uint32_t*)(B1L + (rB + k0) * 2);
            uint32_t bl1 = *(const uint32_t*)(B1L + (rB + k0 + 8) * 2);
            mma16816(acc1[nt], a1H[kt], bh0, bh1);
            mma16816(acc1[nt], a1L[kt], bh0, bh1);
            mma16816(acc1[nt], a1H[kt], bl0, bl1);
        }
    }

    // ---- epilogue 1: bias + snake + dot(W2) + quad reduce ----
    float pr0 = 0.f, pr8 = 0.f;
#pragma unroll
    for (int nt = 0; nt < 8; nt++) {
        int cb = nt * 8 + tid4 * 2;
        float b1a = auxf[64 + cb], b1b = auxf[64 + cb + 1];
        float w2a = auxf[128 + cb], w2b = auxf[128 + cb + 1];
        pr0 = fmaf(snake(acc1[nt][0] + b1a), w2a, pr0);
        pr0 = fmaf(snake(acc1[nt][1] + b1b), w2b, pr0);
        pr8 = fmaf(snake(acc1[nt][2] + b1a), w2a, pr8);
        pr8 = fmaf(snake(acc1[nt][3] + b1b), w2b, pr8);
    }
    pr0 += __shfl_xor_sync(0xffffffffu, pr0, 1);
    pr0 += __shfl_xor_sync(0xffffffffu, pr0, 2);
    pr8 += __shfl_xor_sync(0xffffffffu, pr8, 1);
    pr8 += __shfl_xor_sync(0xffffffffu, pr8, 2);
    if (tid4 == 0) {
        float b2v = __ldg(b2);
        int base = blockIdx.x * PTS_CTA + p0;
        out[base + gid] = pr0 + b2v;
        out[base + gid + 8] = pr8 + b2v;
    }
}

extern "C" void kernel_launch(void* const* d_in, const int* in_sizes, int n_in,
                              void* d_out, int out_size) {
    const float* x      = (const float*)d_in[0];
    const float* gsc    = (const float*)d_in[1];
    const float* gtr    = (const float*)d_in[2];
    const float* fgrids = (const float*)d_in[3];
    const float* W0     = (const float*)d_in[4];
    const float* b0     = (const float*)d_in[5];
    const float* W1     = (const float*)d_in[6];
    const float* b1     = (const float*)d_in[7];
    const float* W2     = (const float*)d_in[8];
    const float* b2     = (const float*)d_in[9];
    float* out          = (float*)d_out;

    cudaFuncSetAttribute(amrsrn_hmma,
                         cudaFuncAttributeMaxDynamicSharedMemorySize,
                         SMEM_TOTAL);

    repack4<<<(NGRIDS * GVOX / 4) / 256, 256>>>(fgrids);
    amrsrn_hmma<<<NPTS / PTS_CTA, THREADS, SMEM_TOTAL>>>(x, gsc, gtr, W0, b0,
                                                         W1, b1, W2, b2, out);
}